// round 6
// baseline (speedup 1.0000x reference)
#include <cuda_runtime.h>
#include <cstdint>

// ---------------------------------------------------------------------------
// HungarianPredictor: B=2048, N=24, D=256
//   cost[b,i,j] = 1 - <normalize(prev[b,i]), normalize(slots[b,j])>
//   col = hungarian(cost)  (Jonker-Volgenant / e-maxx formulation)
//   out[b,i,:] = slots[b, col[b,i], :]
// ---------------------------------------------------------------------------

#define NSLOT   24
#define DDIM    256
#define ROWPAD  260                    // 260*4 = 1040 B row stride: 16B aligned, bank-staggered
#define NN      (NSLOT * NSLOT)        // 576
#define MAXB    2048
#define HINF    1e9f

static const int SMEM_BYTES = 48 * ROWPAD * 4;   // 49,920 B (prev rows 0..23, cur rows 24..47)

__device__ float g_cost[MAXB * NN];
__device__ int   g_col [MAXB * NSLOT];

__device__ __forceinline__ unsigned long long fma2(unsigned long long a,
                                                   unsigned long long b,
                                                   unsigned long long c) {
    unsigned long long d;
    asm("fma.rn.f32x2 %0, %1, %2, %3;" : "=l"(d) : "l"(a), "l"(b), "l"(c));
    return d;
}

// ---------------------------------------------------------------------------
// Kernel 1: per-batch cost matrix.  One block per batch, 256 threads.
// Phases: coalesced load -> row norms -> in-place normalize -> 24x24 dot
// (one warp, 6x3 register tiles, packed f32x2 FMA) -> write cost to global.
// ---------------------------------------------------------------------------
__global__ __launch_bounds__(256)
void cost_kernel(const float* __restrict__ slots, const float* __restrict__ prev) {
    extern __shared__ float s[];
    __shared__ float s_inv[48];
    const int b   = blockIdx.x;
    const int tid = threadIdx.x;

    // ---- load: rows 0..23 = prev, rows 24..47 = slots (cur) ----
    const float4* psrc = (const float4*)(prev  + (size_t)b * (NSLOT * DDIM));
    const float4* csrc = (const float4*)(slots + (size_t)b * (NSLOT * DDIM));
    #pragma unroll
    for (int idx = tid; idx < 48 * 64; idx += 256) {
        int row = idx >> 6, c4 = idx & 63;
        float4 v = (row < NSLOT) ? psrc[row * 64 + c4] : csrc[(row - NSLOT) * 64 + c4];
        *(float4*)&s[row * ROWPAD + c4 * 4] = v;
    }
    __syncthreads();

    // ---- norms: warp w handles rows 6w..6w+5 ----
    {
        int w = tid >> 5, lane = tid & 31;
        #pragma unroll
        for (int rr = 0; rr < 6; ++rr) {
            int r = w * 6 + rr;
            float ss = 0.f;
            #pragma unroll
            for (int k = lane; k < DDIM; k += 32) {
                float x = s[r * ROWPAD + k];
                ss = fmaf(x, x, ss);
            }
            #pragma unroll
            for (int o = 16; o; o >>= 1) ss += __shfl_xor_sync(0xffffffffu, ss, o);
            if (lane == 0) s_inv[r] = 1.f / fmaxf(sqrtf(ss), 1e-12f);
        }
    }
    __syncthreads();

    // ---- normalize in place ----
    for (int idx = tid; idx < 48 * DDIM; idx += 256) {
        int r = idx >> 8, k = idx & 255;
        s[r * ROWPAD + k] *= s_inv[r];
    }
    __syncthreads();

    // ---- cost: one warp (rotated across SMSPs by blockIdx), 6x3 tiles ----
    const int cw = b & 7;
    if ((tid >> 5) == cw) {
        int lane = tid & 31;
        int ty = lane >> 3;          // 0..3 -> 6 rows each
        int tx = lane & 7;           // 0..7 -> 3 cols each
        unsigned long long acc[6][3];
        #pragma unroll
        for (int rr = 0; rr < 6; ++rr)
            #pragma unroll
            for (int cc = 0; cc < 3; ++cc) acc[rr][cc] = 0ull;

        #pragma unroll 4
        for (int k4 = 0; k4 < 64; ++k4) {
            unsigned long long a0[6], a1[6], b0[3], b1[3];
            #pragma unroll
            for (int rr = 0; rr < 6; ++rr) {
                ulonglong2 t = *(const ulonglong2*)&s[(ty * 6 + rr) * ROWPAD + k4 * 4];
                a0[rr] = t.x; a1[rr] = t.y;
            }
            #pragma unroll
            for (int cc = 0; cc < 3; ++cc) {
                ulonglong2 t = *(const ulonglong2*)&s[(NSLOT + tx * 3 + cc) * ROWPAD + k4 * 4];
                b0[cc] = t.x; b1[cc] = t.y;
            }
            #pragma unroll
            for (int rr = 0; rr < 6; ++rr)
                #pragma unroll
                for (int cc = 0; cc < 3; ++cc) {
                    acc[rr][cc] = fma2(a0[rr], b0[cc], acc[rr][cc]);
                    acc[rr][cc] = fma2(a1[rr], b1[cc], acc[rr][cc]);
                }
        }

        float* cg = g_cost + (size_t)b * NN;
        #pragma unroll
        for (int rr = 0; rr < 6; ++rr)
            #pragma unroll
            for (int cc = 0; cc < 3; ++cc) {
                unsigned long long v = acc[rr][cc];
                float lo = __uint_as_float((unsigned)(v & 0xffffffffu));
                float hi = __uint_as_float((unsigned)(v >> 32));
                cg[(ty * 6 + rr) * NSLOT + (tx * 3 + cc)] = 1.f - (lo + hi);
            }
    }
}

// ---------------------------------------------------------------------------
// Kernel 2: Hungarian (JV shortest augmenting path), one warp per batch.
// Lane j owns column j (j=24 is the virtual start column).  All duals in
// registers: v[j], minv[j], way[j], p[j], and up[j] = u[p[j]] (the assigned
// row's potential rides with its column, so no u[] array is needed).
// Argmin = order-preserving uint key + redux.min + ballot/ffs (first-index
// tie-break, identical to jnp.argmin).
// ---------------------------------------------------------------------------
__global__ __launch_bounds__(128)
void hungarian_kernel(int B) {
    __shared__ float sc[4][NN];
    const int w    = threadIdx.x >> 5;
    const int lane = threadIdx.x & 31;
    const int b    = blockIdx.x * 4 + w;
    if (b >= B) return;

    float* c = sc[w];
    const float* cg = g_cost + (size_t)b * NN;
    for (int t = lane; t < NN; t += 32) c[t] = cg[t];
    __syncwarp();

    const unsigned FULL = 0xffffffffu;
    float v  = 0.f;    // column potential
    float up = 0.f;    // u[p[lane]]
    int   p  = -1;     // row assigned to this column

    for (int i = 0; i < NSLOT; ++i) {
        if (lane == NSLOT) { p = i; up = 0.f; }
        float minv = HINF;
        int   way  = 0;
        bool  used = false;
        int   j0   = NSLOT;   // start at virtual column

        for (int it = 0; it < NSLOT + 2; ++it) {
            if (lane == j0) used = true;
            int   i0 = __shfl_sync(FULL, p,  j0);
            float u0 = __shfl_sync(FULL, up, j0);
            float cur = (lane < NSLOT && !used) ? (c[i0 * NSLOT + lane] - u0 - v) : HINF;
            if (cur < minv) { minv = cur; way = j0; }
            float masked = (lane < NSLOT && !used) ? minv : HINF;

            unsigned bits = __float_as_uint(masked);
            unsigned key  = (bits & 0x80000000u) ? ~bits : (bits | 0x80000000u);
            unsigned mkey = __reduce_min_sync(FULL, key);
            float delta   = __uint_as_float((mkey & 0x80000000u) ? (mkey & 0x7fffffffu) : ~mkey);
            unsigned ball = __ballot_sync(FULL, key == mkey);
            int j1 = __ffs(ball) - 1;

            if (used)                { up += delta; v -= delta; }
            else if (lane < NSLOT)   { minv -= delta; }

            j0 = j1;
            int pj = __shfl_sync(FULL, p, j0);
            if (pj < 0) break;
        }

        // augment back along the alternating path to the virtual column
        int j = j0;
        while (j != NSLOT) {
            int   jp  = __shfl_sync(FULL, way, j);
            int   pn_ = __shfl_sync(FULL, p,  jp);
            float un_ = __shfl_sync(FULL, up, jp);
            if (lane == j) { p = pn_; up = un_; }
            j = jp;
        }
    }
    // p[j] = row matched to column j  ->  col_ind[row] = j
    if (lane < NSLOT) g_col[b * NSLOT + p] = lane;
}

// ---------------------------------------------------------------------------
// Kernel 3: gather.  out[b,r,:] = slots[b, col[b,r], :]  (float4 streaming)
// grid = B*6 blocks x 256 threads: exactly one float4 per thread.
// ---------------------------------------------------------------------------
__global__ __launch_bounds__(256)
void gather_kernel(const float* __restrict__ slots, float* __restrict__ out) {
    const int bx = blockIdx.x;
    const int b  = bx / 6;
    const int within = (bx % 6) * 256 + threadIdx.x;   // 0..1535 (float4 idx in batch)
    const int r  = within >> 6;
    const int d4 = within & 63;
    const int src = g_col[b * NSLOT + r];
    const float4* sp = (const float4*)(slots + (size_t)b * (NSLOT * DDIM));
    float4 val = sp[src * 64 + d4];
    ((float4*)(out + (size_t)b * (NSLOT * DDIM)))[r * 64 + d4] = val;
}

// ---------------------------------------------------------------------------
extern "C" void kernel_launch(void* const* d_in, const int* in_sizes, int n_in,
                              void* d_out, int out_size) {
    const float* slots = (const float*)d_in[0];
    const float* prev  = (const float*)d_in[1];
    float* out = (float*)d_out;
    const int B = in_sizes[0] / (NSLOT * DDIM);   // 2048

    cudaFuncSetAttribute(cost_kernel, cudaFuncAttributeMaxDynamicSharedMemorySize, SMEM_BYTES);

    cost_kernel<<<B, 256, SMEM_BYTES>>>(slots, prev);
    hungarian_kernel<<<(B + 3) / 4, 128>>>(B);
    gather_kernel<<<B * 6, 256>>>(slots, out);
}

// round 9
// speedup vs baseline: 1.0864x; 1.0864x over previous
#include <cuda_runtime.h>
#include <cstdint>

// ---------------------------------------------------------------------------
// HungarianPredictor: B=2048, N=24, D=256
//   cost[b,i,j] = 1 - <normalize(prev[b,i]), normalize(slots[b,j])>
//   col = hungarian(cost)  (Jonker-Volgenant / e-maxx formulation)
//   out[b,i,:] = slots[b, col[b,i], :]
// ---------------------------------------------------------------------------

#define NSLOT   24
#define DDIM    256
#define ROWPAD  260                    // 260*4 = 1040 B row stride: 16B aligned, 8-lane-phase conflict-free
#define NN      (NSLOT * NSLOT)        // 576
#define MAXB    2048
#define HINF    1e9f

static const int SMEM_BYTES = 48 * ROWPAD * 4;   // 49,920 B (prev rows 0..23, cur rows 24..47)

__device__ float g_cost[MAXB * NN];
__device__ int   g_col [MAXB * NSLOT];

__device__ __forceinline__ unsigned long long fma2(unsigned long long a,
                                                   unsigned long long b,
                                                   unsigned long long c) {
    unsigned long long d;
    asm("fma.rn.f32x2 %0, %1, %2, %3;" : "=l"(d) : "l"(a), "l"(b), "l"(c));
    return d;
}

__device__ __forceinline__ float hsum2(unsigned long long v) {
    float lo = __uint_as_float((unsigned)(v & 0xffffffffu));
    float hi = __uint_as_float((unsigned)(v >> 32));
    return lo + hi;
}

// ---------------------------------------------------------------------------
// Kernel 1: per-batch cost matrix.  One block per batch, 256 threads.
// Phases: coalesced load -> row norms -> 24x24 dot spread over ALL 8 warps
// (warp w: prev rows 3w..3w+2; lane j: col j; rows broadcast from smem) ->
// epilogue folds the inverse norms: cost = 1 - dot*inv_i*inv_j.
// ---------------------------------------------------------------------------
__global__ __launch_bounds__(256)
void cost_kernel(const float* __restrict__ slots, const float* __restrict__ prev) {
    extern __shared__ float s[];
    __shared__ float s_inv[48];
    const int b   = blockIdx.x;
    const int tid = threadIdx.x;
    const int w   = tid >> 5;
    const int lane = tid & 31;

    // ---- load: rows 0..23 = prev, rows 24..47 = slots (cur) ----
    const float4* psrc = (const float4*)(prev  + (size_t)b * (NSLOT * DDIM));
    const float4* csrc = (const float4*)(slots + (size_t)b * (NSLOT * DDIM));
    #pragma unroll
    for (int idx = tid; idx < 48 * 64; idx += 256) {
        int row = idx >> 6, c4 = idx & 63;
        float4 v = (row < NSLOT) ? psrc[row * 64 + c4] : csrc[(row - NSLOT) * 64 + c4];
        *(float4*)&s[row * ROWPAD + c4 * 4] = v;
    }
    __syncthreads();

    // ---- norms: warp w handles rows 6w..6w+5, store 1/max(norm,eps) ----
    #pragma unroll
    for (int rr = 0; rr < 6; ++rr) {
        int r = w * 6 + rr;
        float ss = 0.f;
        #pragma unroll
        for (int k = lane; k < DDIM; k += 32) {
            float x = s[r * ROWPAD + k];
            ss = fmaf(x, x, ss);
        }
        #pragma unroll
        for (int o = 16; o; o >>= 1) ss += __shfl_xor_sync(0xffffffffu, ss, o);
        if (lane == 0) s_inv[r] = 1.f / fmaxf(sqrtf(ss), 1e-12f);
    }
    __syncthreads();

    // ---- dot: warp w -> prev rows 3w..3w+2, lane j -> cur col j ----
    if (lane < NSLOT) {
        const int r0 = w * 3;
        const float* pr0 = &s[(r0 + 0) * ROWPAD];
        const float* pr1 = &s[(r0 + 1) * ROWPAD];
        const float* pr2 = &s[(r0 + 2) * ROWPAD];
        const float* cj  = &s[(NSLOT + lane) * ROWPAD];

        unsigned long long acc0 = 0ull, acc1 = 0ull, acc2 = 0ull;
        #pragma unroll 4
        for (int k4 = 0; k4 < 64; ++k4) {
            ulonglong2 c  = *(const ulonglong2*)&cj [k4 * 4];   // conflict-free per 8-lane phase
            ulonglong2 a0 = *(const ulonglong2*)&pr0[k4 * 4];   // broadcast
            ulonglong2 a1 = *(const ulonglong2*)&pr1[k4 * 4];   // broadcast
            ulonglong2 a2 = *(const ulonglong2*)&pr2[k4 * 4];   // broadcast
            acc0 = fma2(a0.x, c.x, acc0);  acc0 = fma2(a0.y, c.y, acc0);
            acc1 = fma2(a1.x, c.x, acc1);  acc1 = fma2(a1.y, c.y, acc1);
            acc2 = fma2(a2.x, c.x, acc2);  acc2 = fma2(a2.y, c.y, acc2);
        }

        const float invj = s_inv[NSLOT + lane];
        float* cg = g_cost + (size_t)b * NN;
        cg[(r0 + 0) * NSLOT + lane] = 1.f - hsum2(acc0) * s_inv[r0 + 0] * invj;
        cg[(r0 + 1) * NSLOT + lane] = 1.f - hsum2(acc1) * s_inv[r0 + 1] * invj;
        cg[(r0 + 2) * NSLOT + lane] = 1.f - hsum2(acc2) * s_inv[r0 + 2] * invj;
    }
}

// ---------------------------------------------------------------------------
// Kernel 2: Hungarian (JV shortest augmenting path), one warp per batch.
// Lane j owns column j (j=24 is the virtual start column).  All duals in
// registers: v[j], minv[j], way[j], p[j], and up[j] = u[p[j]].
// Argmin = order-preserving uint key + redux.min + ballot/ffs (first-index
// tie-break, identical to jnp.argmin).
// ---------------------------------------------------------------------------
__global__ __launch_bounds__(128)
void hungarian_kernel(int B) {
    __shared__ float sc[4][NN];
    const int w    = threadIdx.x >> 5;
    const int lane = threadIdx.x & 31;
    const int b    = blockIdx.x * 4 + w;
    if (b >= B) return;

    float* c = sc[w];
    const float* cg = g_cost + (size_t)b * NN;
    for (int t = lane; t < NN; t += 32) c[t] = cg[t];
    __syncwarp();

    const unsigned FULL = 0xffffffffu;
    float v  = 0.f;    // column potential
    float up = 0.f;    // u[p[lane]]
    int   p  = -1;     // row assigned to this column

    for (int i = 0; i < NSLOT; ++i) {
        if (lane == NSLOT) { p = i; up = 0.f; }
        float minv = HINF;
        int   way  = 0;
        bool  used = false;
        int   j0   = NSLOT;   // start at virtual column

        for (int it = 0; it < NSLOT + 2; ++it) {
            if (lane == j0) used = true;
            int   i0 = __shfl_sync(FULL, p,  j0);
            float u0 = __shfl_sync(FULL, up, j0);
            float cur = (lane < NSLOT && !used) ? (c[i0 * NSLOT + lane] - u0 - v) : HINF;
            if (cur < minv) { minv = cur; way = j0; }
            float masked = (lane < NSLOT && !used) ? minv : HINF;

            unsigned bits = __float_as_uint(masked);
            unsigned key  = (bits & 0x80000000u) ? ~bits : (bits | 0x80000000u);
            unsigned mkey = __reduce_min_sync(FULL, key);
            float delta   = __uint_as_float((mkey & 0x80000000u) ? (mkey & 0x7fffffffu) : ~mkey);
            unsigned ball = __ballot_sync(FULL, key == mkey);
            int j1 = __ffs(ball) - 1;

            if (used)                { up += delta; v -= delta; }
            else if (lane < NSLOT)   { minv -= delta; }

            j0 = j1;
            int pj = __shfl_sync(FULL, p, j0);
            if (pj < 0) break;
        }

        // augment back along the alternating path to the virtual column
        int j = j0;
        while (j != NSLOT) {
            int   jp  = __shfl_sync(FULL, way, j);
            int   pn_ = __shfl_sync(FULL, p,  jp);
            float un_ = __shfl_sync(FULL, up, jp);
            if (lane == j) { p = pn_; up = un_; }
            j = jp;
        }
    }
    // p[j] = row matched to column j  ->  col_ind[row] = j
    if (lane < NSLOT) g_col[b * NSLOT + p] = lane;
}

// ---------------------------------------------------------------------------
// Kernel 3: gather.  out[b,r,:] = slots[b, col[b,r], :]  (float4 streaming)
// grid = B*6 blocks x 256 threads: exactly one float4 per thread.
// ---------------------------------------------------------------------------
__global__ __launch_bounds__(256)
void gather_kernel(const float* __restrict__ slots, float* __restrict__ out) {
    const int bx = blockIdx.x;
    const int b  = bx / 6;
    const int within = (bx % 6) * 256 + threadIdx.x;   // 0..1535 (float4 idx in batch)
    const int r  = within >> 6;
    const int d4 = within & 63;
    const int src = g_col[b * NSLOT + r];
    const float4* sp = (const float4*)(slots + (size_t)b * (NSLOT * DDIM));
    float4 val = sp[src * 64 + d4];
    ((float4*)(out + (size_t)b * (NSLOT * DDIM)))[r * 64 + d4] = val;
}

// ---------------------------------------------------------------------------
extern "C" void kernel_launch(void* const* d_in, const int* in_sizes, int n_in,
                              void* d_out, int out_size) {
    const float* slots = (const float*)d_in[0];
    const float* prev  = (const float*)d_in[1];
    float* out = (float*)d_out;
    const int B = in_sizes[0] / (NSLOT * DDIM);   // 2048

    cudaFuncSetAttribute(cost_kernel, cudaFuncAttributeMaxDynamicSharedMemorySize, SMEM_BYTES);

    cost_kernel<<<B, 256, SMEM_BYTES>>>(slots, prev);
    hungarian_kernel<<<(B + 3) / 4, 128>>>(B);
    gather_kernel<<<B * 6, 256>>>(slots, out);
}

// round 10
// speedup vs baseline: 1.1954x; 1.1003x over previous
#include <cuda_runtime.h>
#include <cstdint>

// ---------------------------------------------------------------------------
// HungarianPredictor: B=2048, N=24, D=256
//   cost[b,i,j] = 1 - <normalize(prev[b,i]), normalize(slots[b,j])>
//   col = hungarian(cost)  (Jonker-Volgenant / e-maxx formulation)
//   out[b,i,:] = slots[b, col[b,i], :]
// ---------------------------------------------------------------------------

#define NSLOT   24
#define DDIM    256
#define ROWPAD  260                    // 1040 B row stride: 16B aligned, 8-lane-phase conflict-free
#define NN      (NSLOT * NSLOT)        // 576
#define MAXB    2048
#define HINF    1e9f

static const int SMEM_BYTES = 48 * ROWPAD * 4;   // 49,920 B (prev rows 0..23, cur rows 24..47)

__device__ float g_cost[MAXB * NN];

__device__ __forceinline__ unsigned long long fma2(unsigned long long a,
                                                   unsigned long long b,
                                                   unsigned long long c) {
    unsigned long long d;
    asm("fma.rn.f32x2 %0, %1, %2, %3;" : "=l"(d) : "l"(a), "l"(b), "l"(c));
    return d;
}

__device__ __forceinline__ float hsum2(unsigned long long v) {
    float lo = __uint_as_float((unsigned)(v & 0xffffffffu));
    float hi = __uint_as_float((unsigned)(v >> 32));
    return lo + hi;
}

// ---------------------------------------------------------------------------
// Kernel 1: per-batch cost matrix.  One block per batch, 256 threads.
//   load+norm fused: warp w stages 6 rows (w<4: prev, w>=4: cur) and computes
//   their inverse norms from the load registers (no smem re-read).
//   dot: 4 warps, warp w -> prev rows 6w..6w+5, lane j -> cur col j.
//   epilogue folds the norms: cost = 1 - dot*inv_i*inv_j.
// ---------------------------------------------------------------------------
__global__ __launch_bounds__(256)
void cost_kernel(const float* __restrict__ slots, const float* __restrict__ prev) {
    extern __shared__ float s[];
    __shared__ float s_inv[48];
    const int b    = blockIdx.x;
    const int tid  = threadIdx.x;
    const int w    = tid >> 5;
    const int lane = tid & 31;

    // ---- load 6 rows per warp + fused sum-of-squares ----
    const int srow = (w < 4) ? 6 * w : NSLOT + 6 * (w - 4);
    const float* base = (w < 4) ? (prev  + (size_t)b * (NSLOT * DDIM) + (6 * w) * DDIM)
                                : (slots + (size_t)b * (NSLOT * DDIM) + (6 * (w - 4)) * DDIM);
    float4 v0[6], v1[6];
    #pragma unroll
    for (int rr = 0; rr < 6; ++rr) {               // 12 LDGs in flight
        const float4* rp = (const float4*)(base + rr * DDIM);
        v0[rr] = rp[lane];
        v1[rr] = rp[lane + 32];
    }
    #pragma unroll
    for (int rr = 0; rr < 6; ++rr) {
        *(float4*)&s[(srow + rr) * ROWPAD + lane * 4]        = v0[rr];
        *(float4*)&s[(srow + rr) * ROWPAD + (lane + 32) * 4] = v1[rr];
        float ss = v0[rr].x * v0[rr].x;
        ss = fmaf(v0[rr].y, v0[rr].y, ss);
        ss = fmaf(v0[rr].z, v0[rr].z, ss);
        ss = fmaf(v0[rr].w, v0[rr].w, ss);
        ss = fmaf(v1[rr].x, v1[rr].x, ss);
        ss = fmaf(v1[rr].y, v1[rr].y, ss);
        ss = fmaf(v1[rr].z, v1[rr].z, ss);
        ss = fmaf(v1[rr].w, v1[rr].w, ss);
        #pragma unroll
        for (int o = 16; o; o >>= 1) ss += __shfl_xor_sync(0xffffffffu, ss, o);
        if (lane == 0) s_inv[srow + rr] = 1.f / fmaxf(sqrtf(ss), 1e-12f);
    }
    __syncthreads();

    if (w >= 4) return;                            // dot uses 4 warps (one per SMSP)

    // ---- dot: warp w -> prev rows 6w..6w+5, lane j -> cur col j ----
    if (lane < NSLOT) {
        const int r0 = w * 6;
        const float* cj = &s[(NSLOT + lane) * ROWPAD];
        unsigned long long acc[6];
        #pragma unroll
        for (int rr = 0; rr < 6; ++rr) acc[rr] = 0ull;

        #pragma unroll 4
        for (int k4 = 0; k4 < 64; ++k4) {
            ulonglong2 c = *(const ulonglong2*)&cj[k4 * 4];      // conflict-free per 8-lane phase
            #pragma unroll
            for (int rr = 0; rr < 6; ++rr) {
                ulonglong2 a = *(const ulonglong2*)&s[(r0 + rr) * ROWPAD + k4 * 4];  // broadcast
                acc[rr] = fma2(a.x, c.x, acc[rr]);
                acc[rr] = fma2(a.y, c.y, acc[rr]);
            }
        }

        const float invj = s_inv[NSLOT + lane];
        float* cg = g_cost + (size_t)b * NN;
        #pragma unroll
        for (int rr = 0; rr < 6; ++rr)
            cg[(r0 + rr) * NSLOT + lane] = 1.f - hsum2(acc[rr]) * s_inv[r0 + rr] * invj;
    }
}

// ---------------------------------------------------------------------------
// Kernel 2: Hungarian (one warp per batch) + fused gather.
// Lane j owns column j (j=24 is the virtual start column).  All duals in
// registers: v[j], minv[j], way[j], p[j], up[j]=u[p[j]].  Argmin via
// order-preserving uint key + redux.min + ballot/ffs (first-index tie-break,
// identical to jnp.argmin).  After all 4 warps finish, the block streams the
// gather for its 4 batches (overlaps the serial phase across blocks).
// ---------------------------------------------------------------------------
__global__ __launch_bounds__(128)
void hung_gather_kernel(const float* __restrict__ slots, float* __restrict__ out, int B) {
    __shared__ float sc[4][NN];
    __shared__ int   scol[4][NSLOT];
    const int w    = threadIdx.x >> 5;
    const int lane = threadIdx.x & 31;
    const int b    = blockIdx.x * 4 + w;
    const bool active = (b < B);

    if (active) {
        float* c = sc[w];
        const float* cg = g_cost + (size_t)b * NN;
        for (int t = lane; t < NN; t += 32) c[t] = cg[t];
        __syncwarp();

        const unsigned FULL = 0xffffffffu;
        float v  = 0.f;    // column potential
        float up = 0.f;    // u[p[lane]]
        int   p  = -1;     // row assigned to this column

        for (int i = 0; i < NSLOT; ++i) {
            if (lane == NSLOT) { p = i; up = 0.f; }
            float minv = HINF;
            int   way  = 0;
            bool  used = false;
            int   j0   = NSLOT;   // start at virtual column

            for (int it = 0; it < NSLOT + 2; ++it) {
                if (lane == j0) used = true;
                int   i0 = __shfl_sync(FULL, p,  j0);
                float u0 = __shfl_sync(FULL, up, j0);
                float cur = (lane < NSLOT && !used) ? (c[i0 * NSLOT + lane] - u0 - v) : HINF;
                if (cur < minv) { minv = cur; way = j0; }
                float masked = (lane < NSLOT && !used) ? minv : HINF;

                unsigned bits = __float_as_uint(masked);
                unsigned key  = (bits & 0x80000000u) ? ~bits : (bits | 0x80000000u);
                unsigned mkey = __reduce_min_sync(FULL, key);
                float delta   = __uint_as_float((mkey & 0x80000000u) ? (mkey & 0x7fffffffu) : ~mkey);
                unsigned ball = __ballot_sync(FULL, key == mkey);
                int j1 = __ffs(ball) - 1;

                if (used)                { up += delta; v -= delta; }
                else if (lane < NSLOT)   { minv -= delta; }

                j0 = j1;
                int pj = __shfl_sync(FULL, p, j0);
                if (pj < 0) break;
            }

            // augment back along the alternating path to the virtual column
            int j = j0;
            while (j != NSLOT) {
                int   jp  = __shfl_sync(FULL, way, j);
                int   pn_ = __shfl_sync(FULL, p,  jp);
                float un_ = __shfl_sync(FULL, up, jp);
                if (lane == j) { p = pn_; up = un_; }
                j = jp;
            }
        }
        // p = row matched to column `lane`  ->  col_ind[p] = lane
        if (lane < NSLOT) scol[w][p] = lane;
    }
    __syncthreads();

    // ---- fused gather: 4 batches x 1536 float4, 128 threads ----
    const int b0 = blockIdx.x * 4;
    #pragma unroll
    for (int bb = 0; bb < 4; ++bb) {
        const int bg = b0 + bb;
        if (bg >= B) break;
        const float4* sp = (const float4*)(slots + (size_t)bg * (NSLOT * DDIM));
        float4*       op = (float4*)(out + (size_t)bg * (NSLOT * DDIM));
        #pragma unroll
        for (int idx = threadIdx.x; idx < NSLOT * 64; idx += 128) {
            int r  = idx >> 6;
            int d4 = idx & 63;
            op[idx] = sp[scol[bb][r] * 64 + d4];
        }
    }
}

// ---------------------------------------------------------------------------
extern "C" void kernel_launch(void* const* d_in, const int* in_sizes, int n_in,
                              void* d_out, int out_size) {
    const float* slots = (const float*)d_in[0];
    const float* prev  = (const float*)d_in[1];
    float* out = (float*)d_out;
    const int B = in_sizes[0] / (NSLOT * DDIM);   // 2048

    cudaFuncSetAttribute(cost_kernel, cudaFuncAttributeMaxDynamicSharedMemorySize, SMEM_BYTES);

    cost_kernel<<<B, 256, SMEM_BYTES>>>(slots, prev);
    hung_gather_kernel<<<(B + 3) / 4, 128>>>(slots, out, B);
}